// round 3
// baseline (speedup 1.0000x reference)
#include <cuda_runtime.h>
#include <cuda_bf16.h>
#include <math_constants.h>

// Problem constants
#define BATCH      1024
#define KDIM       256
#define NSAMP      100000
#define INV_TEMP   20.0f

// Tiling
#define BM         128          // batch rows per CTA
#define BN         128          // feature cols per tile
#define KC         64           // K chunk staged in smem for B
#define NTILES     782          // ceil(100000/128)
#define SPLITS     34           // 34 * 23 = 782 exactly
#define TPS        23           // tiles per split

#define AS_STRIDE  132          // padded row stride (floats) for As[k][r]
#define BS_STRIDE  132          // padded row stride (floats) for Bs[k][c]
#define SMEM_A_ELEMS (KDIM * AS_STRIDE)   // 256*132
#define SMEM_B_ELEMS (KC   * BS_STRIDE)   // 64*132
#define SMEM_BYTES  ((SMEM_A_ELEMS + SMEM_B_ELEMS) * 4)   // 168,960 B

// Scratch (no cudaMalloc allowed)
__device__ float g_part_m[SPLITS * BATCH];
__device__ float g_part_s[SPLITS * BATCH];
__device__ float g_row_loss[BATCH];
__device__ int   g_tgt_is64;

// ---------------------------------------------------------------------------
// Detect whether targets buffer is int64 or int32.
// Reads ONLY the first 1024 int32 words (valid under both layouts).
// If int64: odd words are the high halves of values in [0,100000) -> all 0.
// If int32: odd words are random values in [0,100000) -> not all 0.
// ---------------------------------------------------------------------------
__global__ void __launch_bounds__(512)
detect_tgt_kernel(const int* __restrict__ t32)
{
    __shared__ int nz[512];
    int tid = threadIdx.x;
    nz[tid] = (t32[2 * tid + 1] != 0) ? 1 : 0;
    __syncthreads();
    #pragma unroll
    for (int s = 256; s > 0; s >>= 1) {
        if (tid < s) nz[tid] |= nz[tid + s];
        __syncthreads();
    }
    if (tid == 0) g_tgt_is64 = (nz[0] == 0) ? 1 : 0;
}

// ---------------------------------------------------------------------------
// Main kernel: split-K fused GEMM + online logsumexp partials.
// grid = (8 row-blocks, 34 splits), block = 256 threads (16x16), 8x8 microtile.
// A block [128 x 256] resident in smem (transposed), B streamed in 64-k chunks.
// Inner product uses packed fma.rn.f32x2 (2 fp32 FMAs per instr).
// ---------------------------------------------------------------------------
__global__ void __launch_bounds__(256, 1)
lse_main_kernel(const float* __restrict__ inputs, const float* __restrict__ feats)
{
    extern __shared__ float sm[];
    float* As = sm;                     // As[k * AS_STRIDE + r]
    float* Bs = sm + SMEM_A_ELEMS;      // Bs[k * BS_STRIDE + c]

    const int tid = threadIdx.x;
    const int tx  = tid & 15;           // column-thread (8 cols each)
    const int ty  = tid >> 4;           // row-thread (8 rows each)
    const int bm  = blockIdx.x;         // 0..7
    const int sp  = blockIdx.y;         // 0..33
    const int row0 = bm * BM;

    // ---- Load A block [128 x 256] into smem, transposed: As[k][r] ----
    {
        const float4* in4 = reinterpret_cast<const float4*>(inputs + (size_t)row0 * KDIM);
        #pragma unroll
        for (int i = 0; i < 32; ++i) {
            int q  = i * 256 + tid;     // 0..8191 float4 index
            int r  = q >> 6;            // 64 float4 per row
            int k4 = q & 63;
            float4 v = in4[q];
            int k = k4 * 4;
            As[(k + 0) * AS_STRIDE + r] = v.x;
            As[(k + 1) * AS_STRIDE + r] = v.y;
            As[(k + 2) * AS_STRIDE + r] = v.z;
            As[(k + 3) * AS_STRIDE + r] = v.w;
        }
    }

    // Running online-softmax state for this thread's 8 rows (its 8 cols only)
    float rm[8], rs[8];
    #pragma unroll
    for (int i = 0; i < 8; ++i) { rm[i] = -CUDART_INF_F; rs[i] = 0.0f; }

    const int tstart = sp * TPS;

    for (int t = tstart; t < tstart + TPS; ++t) {
        const int col0 = t * BN;

        // 8 rows x 4 col-pairs of packed f32x2 accumulators
        unsigned long long acc[8][4];
        #pragma unroll
        for (int i = 0; i < 8; ++i)
            #pragma unroll
            for (int p = 0; p < 4; ++p) acc[i][p] = 0ull;

        for (int kk = 0; kk < KDIM; kk += KC) {
            __syncthreads();   // previous consumers done with Bs
            // ---- stage Bs[k][c] for k in [0,64), c in [0,128) ----
            #pragma unroll
            for (int i = 0; i < 8; ++i) {
                int q  = i * 256 + tid;  // 0..2047 float4 index
                int c  = q >> 4;         // 16 float4 per feature row chunk
                int k4 = q & 15;
                int gc = col0 + c; if (gc > NSAMP - 1) gc = NSAMP - 1;  // clamp (masked later)
                float4 v = *reinterpret_cast<const float4*>(
                    feats + (size_t)gc * KDIM + kk + k4 * 4);
                int k = k4 * 4;
                Bs[(k + 0) * BS_STRIDE + c] = v.x;
                Bs[(k + 1) * BS_STRIDE + c] = v.y;
                Bs[(k + 2) * BS_STRIDE + c] = v.z;
                Bs[(k + 3) * BS_STRIDE + c] = v.w;
            }
            __syncthreads();

            // ---- compute: 64 k-steps ----
            #pragma unroll 4
            for (int k = 0; k < KC; ++k) {
                const float4* ap = reinterpret_cast<const float4*>(
                    &As[(kk + k) * AS_STRIDE + ty * 8]);
                float4 a0 = ap[0], a1 = ap[1];

                const ulonglong2* bp = reinterpret_cast<const ulonglong2*>(
                    &Bs[k * BS_STRIDE + tx * 8]);
                ulonglong2 bA = bp[0], bB = bp[1];   // 4 packed col-pairs

                float av[8] = {a0.x, a0.y, a0.z, a0.w, a1.x, a1.y, a1.z, a1.w};
                #pragma unroll
                for (int i = 0; i < 8; ++i) {
                    unsigned int au = __float_as_uint(av[i]);
                    unsigned long long a2;
                    asm("mov.b64 %0, {%1, %1};" : "=l"(a2) : "r"(au));
                    asm("fma.rn.f32x2 %0, %1, %2, %0;" : "+l"(acc[i][0]) : "l"(a2), "l"(bA.x));
                    asm("fma.rn.f32x2 %0, %1, %2, %0;" : "+l"(acc[i][1]) : "l"(a2), "l"(bA.y));
                    asm("fma.rn.f32x2 %0, %1, %2, %0;" : "+l"(acc[i][2]) : "l"(a2), "l"(bB.x));
                    asm("fma.rn.f32x2 %0, %1, %2, %0;" : "+l"(acc[i][3]) : "l"(a2), "l"(bB.y));
                }
            }
        }

        // ---- online softmax update for this tile ----
        // 100000 % 8 == 0 and thread covers 8 consecutive cols -> whole-thread validity
        bool active = (col0 + tx * 8) < NSAMP;
        if (active) {
            #pragma unroll
            for (int i = 0; i < 8; ++i) {
                float l[8];
                #pragma unroll
                for (int p = 0; p < 4; ++p) {
                    unsigned int lo, hi;
                    asm("mov.b64 {%0, %1}, %2;" : "=r"(lo), "=r"(hi) : "l"(acc[i][p]));
                    l[2 * p]     = __uint_as_float(lo) * INV_TEMP;
                    l[2 * p + 1] = __uint_as_float(hi) * INV_TEMP;
                }
                float tm = l[0];
                #pragma unroll
                for (int j = 1; j < 8; ++j) tm = fmaxf(tm, l[j]);
                float mnew = fmaxf(rm[i], tm);
                float sc = __expf(rm[i] - mnew);   // exp(-inf) = 0 on first tile
                float ssum = 0.0f;
                #pragma unroll
                for (int j = 0; j < 8; ++j) ssum += __expf(l[j] - mnew);
                rs[i] = rs[i] * sc + ssum;
                rm[i] = mnew;
            }
        }
    }

    // ---- reduce (m,s) across the 16 column-threads sharing each row ----
    #pragma unroll
    for (int i = 0; i < 8; ++i) {
        float m = rm[i], s = rs[i];
        #pragma unroll
        for (int off = 8; off >= 1; off >>= 1) {
            float mo = __shfl_xor_sync(0xffffffffu, m, off);
            float so = __shfl_xor_sync(0xffffffffu, s, off);
            float mn = fmaxf(m, mo);
            s = s * __expf(m - mn) + so * __expf(mo - mn);
            m = mn;
        }
        if (tx == 0) {
            int row = row0 + ty * 8 + i;
            g_part_m[sp * BATCH + row] = m;
            g_part_s[sp * BATCH + row] = s;
        }
    }
}

// ---------------------------------------------------------------------------
// Finalize: one warp per batch row. Combine SPLITS partials into logsumexp,
// compute target logit via a warp dot product, write per-row loss.
// ---------------------------------------------------------------------------
__global__ void __launch_bounds__(256)
lse_finalize_kernel(const float* __restrict__ inputs,
                    const void* __restrict__ targets,
                    const float* __restrict__ feats)
{
    int gwarp = (blockIdx.x * blockDim.x + threadIdx.x) >> 5;  // 0..1023
    int lane  = threadIdx.x & 31;
    if (gwarp >= BATCH) return;
    int b = gwarp;

    // target index, dtype-agnostic (flag set by detect_tgt_kernel)
    long long tgt;
    if (g_tgt_is64) tgt = ((const long long*)targets)[b];
    else            tgt = (long long)((const int*)targets)[b];
    if (tgt < 0) tgt = 0;
    if (tgt >= NSAMP) tgt = NSAMP - 1;

    const float* xr = inputs + (size_t)b * KDIM;
    const float* fr = feats + (size_t)tgt * KDIM;
    float d = 0.0f;
    #pragma unroll
    for (int j = 0; j < 8; ++j)
        d += xr[lane + 32 * j] * fr[lane + 32 * j];
    #pragma unroll
    for (int off = 16; off >= 1; off >>= 1)
        d += __shfl_xor_sync(0xffffffffu, d, off);
    float target_logit = d * INV_TEMP;

    // combine split partials (each lane owns <=2 of the 34 partials)
    float m = -CUDART_INF_F, s = 0.0f;
    for (int idx = lane; idx < SPLITS; idx += 32) {
        float pm = g_part_m[idx * BATCH + b];
        float ps = g_part_s[idx * BATCH + b];
        float mn = fmaxf(m, pm);
        s = s * __expf(m - mn) + ps * __expf(pm - mn);
        m = mn;
    }
    #pragma unroll
    for (int off = 16; off >= 1; off >>= 1) {
        float mo = __shfl_xor_sync(0xffffffffu, m, off);
        float so = __shfl_xor_sync(0xffffffffu, s, off);
        float mn = fmaxf(m, mo);
        s = s * __expf(m - mn) + so * __expf(mo - mn);
        m = mn;
    }
    if (lane == 0)
        g_row_loss[b] = (m + logf(s)) - target_logit;
}

// ---------------------------------------------------------------------------
// Deterministic mean over 1024 row losses.
// ---------------------------------------------------------------------------
__global__ void __launch_bounds__(256)
lse_mean_kernel(float* __restrict__ out)
{
    __shared__ float red[256];
    int tid = threadIdx.x;
    float v = g_row_loss[tid] + g_row_loss[tid + 256] +
              g_row_loss[tid + 512] + g_row_loss[tid + 768];
    red[tid] = v;
    __syncthreads();
    #pragma unroll
    for (int s = 128; s > 0; s >>= 1) {
        if (tid < s) red[tid] += red[tid + s];
        __syncthreads();
    }
    if (tid == 0) out[0] = red[0] * (1.0f / 1024.0f);
}

// ---------------------------------------------------------------------------
extern "C" void kernel_launch(void* const* d_in, const int* in_sizes, int n_in,
                              void* d_out, int out_size)
{
    const float* inputs  = (const float*)d_in[0];   // [1024, 256] f32
    const void*  targets = d_in[1];                 // [1024] int32 or int64
    const float* feats   = (const float*)d_in[2];   // [100000, 256] f32
    float*       out     = (float*)d_out;           // scalar f32

    cudaFuncSetAttribute(lse_main_kernel,
                         cudaFuncAttributeMaxDynamicSharedMemorySize, SMEM_BYTES);

    detect_tgt_kernel<<<1, 512>>>((const int*)targets);
    dim3 grid(8, SPLITS);
    lse_main_kernel<<<grid, 256, SMEM_BYTES>>>(inputs, feats);
    lse_finalize_kernel<<<128, 256>>>(inputs, targets, feats);
    lse_mean_kernel<<<1, 256>>>(out);
}